// round 7
// baseline (speedup 1.0000x reference)
#include <cuda_runtime.h>
#include <cuda_bf16.h>
#include <cstdint>

#define NMAX 100000
#define EMAX 800000
#define DIM 128

// ---------------------------------------------------------------------------
// Scratch (__device__ globals per allocation-free rule)
// ---------------------------------------------------------------------------
// Packed A operand: [N][384] bf16 hi/lo planes (scales folded in)
__device__ __align__(16) __nv_bfloat16 g_Ahi[(size_t)NMAX * 384];
__device__ __align__(16) __nv_bfloat16 g_Alo[(size_t)NMAX * 384];
// Weights, bf16 split, TRANSPOSED to [chunk][n][k]  (B[n][k] = W[k][n])
__device__ __align__(16) __nv_bfloat16 g_Bhi[3 * 128 * 128];
__device__ __align__(16) __nv_bfloat16 g_Blo[3 * 128 * 128];
// CSR machinery
__device__ int g_hist_in[NMAX];
__device__ int g_hist_out[NMAX];
__device__ int g_rp_in[NMAX + 1];
__device__ int g_rp_out[NMAX + 1];
__device__ int g_cur_in[NMAX];
__device__ int g_cur_out[NMAX];
__device__ int g_in_src[EMAX];    // src ids grouped by dst
__device__ int g_out_dst[EMAX];   // dst ids grouped by src

// ---------------------------------------------------------------------------
// helpers
// ---------------------------------------------------------------------------
__device__ __forceinline__ int clamp_idx(int v, int n) {
    return v < 0 ? 0 : (v >= n ? n - 1 : v);
}

__device__ __forceinline__ uint32_t smem_u32(const void* p) {
    uint32_t a;
    asm("{ .reg .u64 t; cvta.to.shared.u64 t, %1; cvt.u32.u64 %0, t; }"
        : "=r"(a) : "l"(p));
    return a;
}

__device__ __forceinline__ void cp_async16(uint32_t dst, const void* src) {
    asm volatile("cp.async.cg.shared.global [%0], [%1], 16;"
                 :: "r"(dst), "l"(src) : "memory");
}
__device__ __forceinline__ void cp_commit() {
    asm volatile("cp.async.commit_group;" ::: "memory");
}
__device__ __forceinline__ void cp_wait1() {
    asm volatile("cp.async.wait_group 1;" ::: "memory");
}

__device__ __forceinline__ void ldsm_x4(uint32_t* r, uint32_t addr) {
    asm volatile("ldmatrix.sync.aligned.m8n8.x4.shared.b16 {%0,%1,%2,%3}, [%4];"
                 : "=r"(r[0]), "=r"(r[1]), "=r"(r[2]), "=r"(r[3]) : "r"(addr));
}

__device__ __forceinline__ void mma_bf16(float* d, const uint32_t* a,
                                         uint32_t b0, uint32_t b1) {
    asm volatile(
        "mma.sync.aligned.m16n8k16.row.col.f32.bf16.bf16.f32 "
        "{%0,%1,%2,%3}, {%4,%5,%6,%7}, {%8,%9}, {%0,%1,%2,%3};"
        : "+f"(d[0]), "+f"(d[1]), "+f"(d[2]), "+f"(d[3])
        : "r"(a[0]), "r"(a[1]), "r"(a[2]), "r"(a[3]), "r"(b0), "r"(b1));
}

// split float4 -> bf16 hi/lo packed as uint2 each
__device__ __forceinline__ void split4(float4 v, uint2& hi, uint2& lo) {
    __nv_bfloat16 hx = __float2bfloat16(v.x);
    __nv_bfloat16 hy = __float2bfloat16(v.y);
    __nv_bfloat16 hz = __float2bfloat16(v.z);
    __nv_bfloat16 hw = __float2bfloat16(v.w);
    __nv_bfloat162 h01; h01.x = hx; h01.y = hy;
    __nv_bfloat162 h23; h23.x = hz; h23.y = hw;
    __nv_bfloat162 l01;
    l01.x = __float2bfloat16(v.x - __bfloat162float(hx));
    l01.y = __float2bfloat16(v.y - __bfloat162float(hy));
    __nv_bfloat162 l23;
    l23.x = __float2bfloat16(v.z - __bfloat162float(hz));
    l23.y = __float2bfloat16(v.w - __bfloat162float(hw));
    hi = make_uint2(*reinterpret_cast<uint32_t*>(&h01),
                    *reinterpret_cast<uint32_t*>(&h23));
    lo = make_uint2(*reinterpret_cast<uint32_t*>(&l01),
                    *reinterpret_cast<uint32_t*>(&l23));
}

// ---------------------------------------------------------------------------
// CSR build: zero hist -> histogram -> single-block scan -> place
// ---------------------------------------------------------------------------
__global__ void zero_hist_kernel(int n) {
    int i = blockIdx.x * blockDim.x + threadIdx.x;
    if (i < n) { g_hist_in[i] = 0; g_hist_out[i] = 0; }
}

__global__ void hist_kernel(const int* __restrict__ ei, int E, int n) {
    int e = blockIdx.x * blockDim.x + threadIdx.x;
    if (e >= E) return;
    int src = clamp_idx(__ldg(&ei[e]), n);
    int dst = clamp_idx(__ldg(&ei[E + e]), n);
    atomicAdd(&g_hist_in[dst],  1);
    atomicAdd(&g_hist_out[src], 1);
}

__global__ void __launch_bounds__(1024)
scan_kernel(int n) {
    __shared__ int sh[1024];
    const int t = threadIdx.x;
    const int chunk = (n + 1023) / 1024;
    const int begin = t * chunk;
    const int end   = min(begin + chunk, n);

#pragma unroll 1
    for (int d = 0; d < 2; d++) {
        const int* hist = d == 0 ? g_hist_in : g_hist_out;
        int* rp  = d == 0 ? g_rp_in  : g_rp_out;
        int* cur = d == 0 ? g_cur_in : g_cur_out;

        int s = 0;
        for (int i = begin; i < end; i++) s += hist[i];
        sh[t] = s;
        __syncthreads();
        // Hillis-Steele inclusive scan over 1024 partials
        for (int off = 1; off < 1024; off <<= 1) {
            int tmp = (t >= off) ? sh[t - off] : 0;
            __syncthreads();
            sh[t] += tmp;
            __syncthreads();
        }
        int run = (t == 0) ? 0 : sh[t - 1];
        for (int i = begin; i < end; i++) {
            rp[i] = run;
            cur[i] = run;
            run += hist[i];
        }
        if (begin < n && end == n) rp[n] = run;
        __syncthreads();
    }
}

__global__ void place_kernel(const int* __restrict__ ei, int E, int n) {
    int e = blockIdx.x * blockDim.x + threadIdx.x;
    if (e >= E) return;
    int src = clamp_idx(__ldg(&ei[e]), n);
    int dst = clamp_idx(__ldg(&ei[E + e]), n);
    int p0 = atomicAdd(&g_cur_in[dst], 1);
    g_in_src[p0] = src;
    int p1 = atomicAdd(&g_cur_out[src], 1);
    g_out_dst[p1] = dst;
}

// ---------------------------------------------------------------------------
// Weight prep: split fp32 W[k][n] -> bf16 hi/lo, transposed to [n][k]
// ---------------------------------------------------------------------------
__global__ void prep_weights(const float* __restrict__ Wself,
                             const float* __restrict__ Ws2d,
                             const float* __restrict__ Wd2s) {
    int idx = blockIdx.x * blockDim.x + threadIdx.x;
    if (idx >= 3 * 16384) return;
    int chunk = idx >> 14;
    int rem   = idx & 16383;
    int k  = rem >> 7;
    int nn = rem & 127;
    const float* W = (chunk == 0) ? Wself : (chunk == 1) ? Ws2d : Wd2s;
    float w = __ldg(&W[k * 128 + nn]);
    __nv_bfloat16 hi = __float2bfloat16(w);
    float lo = w - __bfloat162float(hi);
    g_Bhi[chunk * 16384 + nn * 128 + k] = hi;
    g_Blo[chunk * 16384 + nn * 128 + k] = __float2bfloat16(lo);
}

// ---------------------------------------------------------------------------
// Gather: one warp per node, accumulate neighbor rows in registers, write
// packed bf16 hi/lo with 0.5/deg folded in. DIR 0 (in) also packs chunk 0 (x).
// ---------------------------------------------------------------------------
template<int DIR>
__global__ void __launch_bounds__(256)
gather_kernel(const float* __restrict__ x, int n) {
    int node = (blockIdx.x * blockDim.x + threadIdx.x) >> 5;
    int lane = threadIdx.x & 31;
    if (node >= n) return;

    const int* rp    = (DIR == 0) ? g_rp_in  : g_rp_out;
    const int* elist = (DIR == 0) ? g_in_src : g_out_dst;
    const int b  = rp[node];
    const int e2 = rp[node + 1];
    const int deg = e2 - b;

    float4 acc = make_float4(0.f, 0.f, 0.f, 0.f);
    int j = b;
    for (; j + 4 <= e2; j += 4) {
        int i0 = __ldg(&elist[j + 0]);
        int i1 = __ldg(&elist[j + 1]);
        int i2 = __ldg(&elist[j + 2]);
        int i3 = __ldg(&elist[j + 3]);
        float4 v0 = __ldg(reinterpret_cast<const float4*>(x + (size_t)i0 * DIM) + lane);
        float4 v1 = __ldg(reinterpret_cast<const float4*>(x + (size_t)i1 * DIM) + lane);
        float4 v2 = __ldg(reinterpret_cast<const float4*>(x + (size_t)i2 * DIM) + lane);
        float4 v3 = __ldg(reinterpret_cast<const float4*>(x + (size_t)i3 * DIM) + lane);
        acc.x += v0.x + v1.x + v2.x + v3.x;
        acc.y += v0.y + v1.y + v2.y + v3.y;
        acc.z += v0.z + v1.z + v2.z + v3.z;
        acc.w += v0.w + v1.w + v2.w + v3.w;
    }
    for (; j < e2; j++) {
        int i0 = __ldg(&elist[j]);
        float4 v0 = __ldg(reinterpret_cast<const float4*>(x + (size_t)i0 * DIM) + lane);
        acc.x += v0.x; acc.y += v0.y; acc.z += v0.z; acc.w += v0.w;
    }

    const float s = 0.5f / fmaxf((float)deg, 1.f);
    acc.x *= s; acc.y *= s; acc.z *= s; acc.w *= s;

    uint2 hi, lo;
    split4(acc, hi, lo);
    const size_t off = (size_t)node * 384 + (DIR == 0 ? 128 : 256) + lane * 4;
    *reinterpret_cast<uint2*>(g_Ahi + off) = hi;
    *reinterpret_cast<uint2*>(g_Alo + off) = lo;

    if (DIR == 0) {
        float4 v = __ldg(reinterpret_cast<const float4*>(x + (size_t)node * DIM) + lane);
        split4(v, hi, lo);
        const size_t o0 = (size_t)node * 384 + lane * 4;
        *reinterpret_cast<uint2*>(g_Ahi + o0) = hi;
        *reinterpret_cast<uint2*>(g_Alo + o0) = lo;
    }
}

// ---------------------------------------------------------------------------
// Pure-bf16 GEMM, cp.async 2-stage pipeline, occupancy 2:
//   out[N,128] = A[N,384] @ W(384x128) + bias, 3-term split hi/lo.
// BM=128, BN=64, BK=64 (6 steps); 8 warps, warp tile 32x32.
// Stage = A_hi|A_lo (128x144B) + B_hi|B_lo (64x144B) = 55296B; x2 = 110592.
// ---------------------------------------------------------------------------
#define TSTRIDE 144
#define APLANE  (128 * TSTRIDE)          // 18432
#define BPLANE  (64 * TSTRIDE)           // 9216
#define STAGE   (2 * APLANE + 2 * BPLANE)  // 55296

__global__ void __launch_bounds__(256, 2)
gemm_mma_kernel(const float* __restrict__ bself,
                const float* __restrict__ bs2d,
                const float* __restrict__ bd2s,
                float* __restrict__ out, int n) {
    extern __shared__ char smem[];
    const uint32_t sbase = smem_u32(smem);

    const int tid  = threadIdx.x;
    const int lane = tid & 31;
    const int wid  = tid >> 5;
    const int block_row = blockIdx.x * 128;
    const int ncol_base = blockIdx.y * 64;

    // warp tile: 32 rows x 32 cols
    const int m0  = (wid & 3) * 32;
    const int n0l = (wid >> 2) * 32;      // local within 64-col block

    // A fill: 2 threads/row, 64B each
    const int frow = tid >> 1;
    const int half = tid & 1;
    const int grow = min(block_row + frow, n - 1);
    // B fill: tid<128, 2 threads/row over 64 rows
    const int brow  = (tid & 127) >> 1;
    const int bhalf = tid & 1;

    auto issue_stage = [&](int s, int st) {
        const uint32_t buf = sbase + st * STAGE;
        // A planes
        {
            const uint32_t d = (uint32_t)frow * TSTRIDE + half * 64;
            const char* srcAh = (const char*)(g_Ahi + (size_t)grow * 384 + s * 64)
                              + half * 64;
            const char* srcAl = (const char*)(g_Alo + (size_t)grow * 384 + s * 64)
                              + half * 64;
#pragma unroll
            for (int jj = 0; jj < 4; jj++) {
                cp_async16(buf + d + jj * 16, srcAh + jj * 16);
                cp_async16(buf + APLANE + d + jj * 16, srcAl + jj * 16);
            }
        }
        // B planes (first 128 threads)
        if (tid < 128) {
            const int chunk = s >> 1;
            const int kh    = s & 1;
            const uint32_t d = (uint32_t)brow * TSTRIDE + bhalf * 64;
            const char* srcBh = (const char*)(g_Bhi + chunk * 16384
                                + (size_t)(ncol_base + brow) * 128 + kh * 64)
                              + bhalf * 64;
            const char* srcBl = (const char*)(g_Blo + chunk * 16384
                                + (size_t)(ncol_base + brow) * 128 + kh * 64)
                              + bhalf * 64;
#pragma unroll
            for (int jj = 0; jj < 4; jj++) {
                cp_async16(buf + 2 * APLANE + d + jj * 16, srcBh + jj * 16);
                cp_async16(buf + 2 * APLANE + BPLANE + d + jj * 16, srcBl + jj * 16);
            }
        }
    };

    const uint32_t offA = (uint32_t)(m0 + (lane & 15)) * TSTRIDE + ((lane >> 4) << 4);
    const uint32_t offB = (uint32_t)(n0l + ((lane >> 4) << 3) + (lane & 7)) * TSTRIDE
                        + (((lane >> 3) & 1) << 4);

    float acc[2][4][4];
#pragma unroll
    for (int m = 0; m < 2; m++)
#pragma unroll
        for (int f = 0; f < 4; f++)
#pragma unroll
            for (int r = 0; r < 4; r++) acc[m][f][r] = 0.f;

    issue_stage(0, 0); cp_commit();
    issue_stage(1, 1); cp_commit();

#pragma unroll 1
    for (int s = 0; s < 6; s++) {
        cp_wait1();
        __syncthreads();

        const uint32_t buf = sbase + (s & 1) * STAGE;
        const uint32_t aHi = buf, aLo = buf + APLANE;
        const uint32_t bHi = buf + 2 * APLANE, bLo = bHi + BPLANE;

#pragma unroll
        for (int ks = 0; ks < 4; ks++) {
            const uint32_t kb = (uint32_t)ks * 32;

            uint32_t ah[2][4], al[2][4];
#pragma unroll
            for (int m = 0; m < 2; m++) {
                uint32_t a = offA + (uint32_t)m * 16 * TSTRIDE + kb;
                ldsm_x4(ah[m], aHi + a);
                ldsm_x4(al[m], aLo + a);
            }
#pragma unroll
            for (int g = 0; g < 2; g++) {
                uint32_t b = offB + (uint32_t)g * 16 * TSTRIDE + kb;
                uint32_t bh[4], bl[4];
                ldsm_x4(bh, bHi + b);
                ldsm_x4(bl, bLo + b);
#pragma unroll
                for (int m = 0; m < 2; m++) {
                    mma_bf16(acc[m][2 * g + 0], ah[m], bh[0], bh[1]);
                    mma_bf16(acc[m][2 * g + 1], ah[m], bh[2], bh[3]);
                    mma_bf16(acc[m][2 * g + 0], ah[m], bl[0], bl[1]);
                    mma_bf16(acc[m][2 * g + 1], ah[m], bl[2], bl[3]);
                    mma_bf16(acc[m][2 * g + 0], al[m], bh[0], bh[1]);
                    mma_bf16(acc[m][2 * g + 1], al[m], bh[2], bh[3]);
                }
            }
        }

        __syncthreads();
        if (s + 2 < 6) issue_stage(s + 2, s & 1);
        cp_commit();
    }

    // ---- Epilogue: fused bias = b_self + 0.5*(b_s2d + b_d2s)
    const int colq = (lane & 3) * 2;
    const int rowq = lane >> 2;
#pragma unroll
    for (int f = 0; f < 4; f++) {
        int col = ncol_base + n0l + f * 8 + colq;
        float b0 = __ldg(&bself[col])     + 0.5f * (__ldg(&bs2d[col])     + __ldg(&bd2s[col]));
        float b1 = __ldg(&bself[col + 1]) + 0.5f * (__ldg(&bs2d[col + 1]) + __ldg(&bd2s[col + 1]));
#pragma unroll
        for (int m = 0; m < 2; m++) {
            int r0 = block_row + m0 + m * 16 + rowq;
#pragma unroll
            for (int h = 0; h < 2; h++) {
                int row = r0 + h * 8;
                if (row < n) {
                    float2 v = make_float2(acc[m][f][2 * h] + b0,
                                           acc[m][f][2 * h + 1] + b1);
                    *reinterpret_cast<float2*>(out + (size_t)row * DIM + col) = v;
                }
            }
        }
    }
}

// ---------------------------------------------------------------------------
// Launch
// ---------------------------------------------------------------------------
extern "C" void kernel_launch(void* const* d_in, const int* in_sizes, int n_in,
                              void* d_out, int out_size) {
    const float* x     = (const float*)d_in[0];
    const float* Wself = (const float*)d_in[1];
    const float* bself = (const float*)d_in[2];
    const float* Ws2d  = (const float*)d_in[3];
    const float* bs2d  = (const float*)d_in[4];
    const float* Wd2s  = (const float*)d_in[5];
    const float* bd2s  = (const float*)d_in[6];
    const int*   ei    = (const int*)d_in[7];

    int N = in_sizes[0] / DIM;      // 100000
    int E = in_sizes[7] / 2;        // 800000
    float* out = (float*)d_out;

    const int smem_bytes = 2 * STAGE;   // 110592
    cudaFuncSetAttribute(gemm_mma_kernel,
                         cudaFuncAttributeMaxDynamicSharedMemorySize, smem_bytes);

    prep_weights<<<(3 * 16384 + 255) / 256, 256>>>(Wself, Ws2d, Wd2s);

    zero_hist_kernel<<<(N + 255) / 256, 256>>>(N);
    hist_kernel<<<(E + 255) / 256, 256>>>(ei, E, N);
    scan_kernel<<<1, 1024>>>(N);
    place_kernel<<<(E + 255) / 256, 256>>>(ei, E, N);

    gather_kernel<0><<<(N * 32 + 255) / 256, 256>>>(x, N);
    gather_kernel<1><<<(N * 32 + 255) / 256, 256>>>(x, N);

    dim3 grid((N + 127) / 128, 2);
    gemm_mma_kernel<<<grid, 256, smem_bytes>>>(bself, bs2d, bd2s, out, N);
}

// round 8
// speedup vs baseline: 2.2345x; 2.2345x over previous
#include <cuda_runtime.h>
#include <cuda_bf16.h>
#include <cstdint>

#define NMAX 100000
#define EMAX 800000
#define DIM 128
#define SCAN_BLK 1024
#define NBLK_MAX 128

// ---------------------------------------------------------------------------
// Scratch (__device__ globals per allocation-free rule)
// ---------------------------------------------------------------------------
// Packed A operand: [N][384] bf16 hi/lo planes (scales folded in)
__device__ __align__(16) __nv_bfloat16 g_Ahi[(size_t)NMAX * 384];
__device__ __align__(16) __nv_bfloat16 g_Alo[(size_t)NMAX * 384];
// Weights, bf16 split, TRANSPOSED to [chunk][n][k]  (B[n][k] = W[k][n])
__device__ __align__(16) __nv_bfloat16 g_Bhi[3 * 128 * 128];
__device__ __align__(16) __nv_bfloat16 g_Blo[3 * 128 * 128];
// CSR machinery
__device__ int g_hist_in[NMAX];
__device__ int g_hist_out[NMAX];
__device__ int g_rp_in[NMAX + 1];
__device__ int g_rp_out[NMAX + 1];
__device__ int g_cur_in[NMAX];
__device__ int g_cur_out[NMAX];
__device__ int g_part_in[NMAX];
__device__ int g_part_out[NMAX];
__device__ int g_bsum[2][NBLK_MAX];
__device__ int g_boff[2][NBLK_MAX];
__device__ int g_in_src[EMAX];    // src ids grouped by dst
__device__ int g_out_dst[EMAX];   // dst ids grouped by src

// ---------------------------------------------------------------------------
// helpers
// ---------------------------------------------------------------------------
__device__ __forceinline__ int clamp_idx(int v, int n) {
    return v < 0 ? 0 : (v >= n ? n - 1 : v);
}

__device__ __forceinline__ uint32_t smem_u32(const void* p) {
    uint32_t a;
    asm("{ .reg .u64 t; cvta.to.shared.u64 t, %1; cvt.u32.u64 %0, t; }"
        : "=r"(a) : "l"(p));
    return a;
}

__device__ __forceinline__ void cp_async16(uint32_t dst, const void* src) {
    asm volatile("cp.async.cg.shared.global [%0], [%1], 16;"
                 :: "r"(dst), "l"(src) : "memory");
}
__device__ __forceinline__ void cp_commit() {
    asm volatile("cp.async.commit_group;" ::: "memory");
}
__device__ __forceinline__ void cp_wait1() {
    asm volatile("cp.async.wait_group 1;" ::: "memory");
}

__device__ __forceinline__ void ldsm_x4(uint32_t* r, uint32_t addr) {
    asm volatile("ldmatrix.sync.aligned.m8n8.x4.shared.b16 {%0,%1,%2,%3}, [%4];"
                 : "=r"(r[0]), "=r"(r[1]), "=r"(r[2]), "=r"(r[3]) : "r"(addr));
}

__device__ __forceinline__ void mma_bf16(float* d, const uint32_t* a,
                                         uint32_t b0, uint32_t b1) {
    asm volatile(
        "mma.sync.aligned.m16n8k16.row.col.f32.bf16.bf16.f32 "
        "{%0,%1,%2,%3}, {%4,%5,%6,%7}, {%8,%9}, {%0,%1,%2,%3};"
        : "+f"(d[0]), "+f"(d[1]), "+f"(d[2]), "+f"(d[3])
        : "r"(a[0]), "r"(a[1]), "r"(a[2]), "r"(a[3]), "r"(b0), "r"(b1));
}

// split float4 -> bf16 hi/lo packed as uint2 each
__device__ __forceinline__ void split4(float4 v, uint2& hi, uint2& lo) {
    __nv_bfloat16 hx = __float2bfloat16(v.x);
    __nv_bfloat16 hy = __float2bfloat16(v.y);
    __nv_bfloat16 hz = __float2bfloat16(v.z);
    __nv_bfloat16 hw = __float2bfloat16(v.w);
    __nv_bfloat162 h01; h01.x = hx; h01.y = hy;
    __nv_bfloat162 h23; h23.x = hz; h23.y = hw;
    __nv_bfloat162 l01;
    l01.x = __float2bfloat16(v.x - __bfloat162float(hx));
    l01.y = __float2bfloat16(v.y - __bfloat162float(hy));
    __nv_bfloat162 l23;
    l23.x = __float2bfloat16(v.z - __bfloat162float(hz));
    l23.y = __float2bfloat16(v.w - __bfloat162float(hw));
    hi = make_uint2(*reinterpret_cast<uint32_t*>(&h01),
                    *reinterpret_cast<uint32_t*>(&h23));
    lo = make_uint2(*reinterpret_cast<uint32_t*>(&l01),
                    *reinterpret_cast<uint32_t*>(&l23));
}

// ---------------------------------------------------------------------------
// CSR build: hist -> 3-phase parallel exclusive scan -> place
// ---------------------------------------------------------------------------
__global__ void zero_hist_kernel(int n) {
    int i = blockIdx.x * blockDim.x + threadIdx.x;
    if (i < n) { g_hist_in[i] = 0; g_hist_out[i] = 0; }
}

__global__ void hist_kernel(const int* __restrict__ ei, int E, int n) {
    int e = blockIdx.x * blockDim.x + threadIdx.x;
    if (e >= E) return;
    int src = clamp_idx(__ldg(&ei[e]), n);
    int dst = clamp_idx(__ldg(&ei[E + e]), n);
    atomicAdd(&g_hist_in[dst],  1);
    atomicAdd(&g_hist_out[src], 1);
}

// phase 1: per-block exclusive scan (1024 elems/block), emit block totals
__global__ void __launch_bounds__(SCAN_BLK)
scan1_kernel(int n) {
    const int dir = blockIdx.y;
    const int b   = blockIdx.x;
    const int i   = b * SCAN_BLK + threadIdx.x;
    const int lane = threadIdx.x & 31;
    const int w    = threadIdx.x >> 5;

    const int* hist = (dir == 0) ? g_hist_in : g_hist_out;
    int v = (i < n) ? hist[i] : 0;

    // warp inclusive scan
    int x = v;
#pragma unroll
    for (int o = 1; o < 32; o <<= 1) {
        int t = __shfl_up_sync(~0u, x, o);
        if (lane >= o) x += t;
    }
    __shared__ int wsum[32];
    if (lane == 31) wsum[w] = x;
    __syncthreads();
    if (w == 0) {
        int y = wsum[lane];
#pragma unroll
        for (int o = 1; o < 32; o <<= 1) {
            int t = __shfl_up_sync(~0u, y, o);
            if (lane >= o) y += t;
        }
        wsum[lane] = y;
    }
    __syncthreads();
    int incl = x + (w > 0 ? wsum[w - 1] : 0);

    int* part = (dir == 0) ? g_part_in : g_part_out;
    if (i < n) part[i] = incl - v;
    if (threadIdx.x == SCAN_BLK - 1) g_bsum[dir][b] = incl;
}

// phase 2: scan block totals (warp 0: dir 0, warp 1: dir 1); write rp[n]
__global__ void scan2_kernel(int nblk, int n) {
    const int dir  = threadIdx.x >> 5;
    const int lane = threadIdx.x & 31;
    if (dir >= 2) return;
    int run = 0;
    for (int base = 0; base < nblk; base += 32) {
        int idx = base + lane;
        int v = (idx < nblk) ? g_bsum[dir][idx] : 0;
        int x = v;
#pragma unroll
        for (int o = 1; o < 32; o <<= 1) {
            int t = __shfl_up_sync(~0u, x, o);
            if (lane >= o) x += t;
        }
        if (idx < nblk) g_boff[dir][idx] = run + x - v;
        run += __shfl_sync(~0u, x, 31);
    }
    if (lane == 0) ((dir == 0) ? g_rp_in : g_rp_out)[n] = run;
}

// phase 3: add block offsets, write rp and cur
__global__ void __launch_bounds__(SCAN_BLK)
scan3_kernel(int n) {
    const int dir = blockIdx.y;
    const int i   = blockIdx.x * SCAN_BLK + threadIdx.x;
    if (i >= n) return;
    const int off = g_boff[dir][blockIdx.x];
    int val = ((dir == 0) ? g_part_in : g_part_out)[i] + off;
    if (dir == 0) { g_rp_in[i]  = val; g_cur_in[i]  = val; }
    else          { g_rp_out[i] = val; g_cur_out[i] = val; }
}

__global__ void place_kernel(const int* __restrict__ ei, int E, int n) {
    int e = blockIdx.x * blockDim.x + threadIdx.x;
    if (e >= E) return;
    int src = clamp_idx(__ldg(&ei[e]), n);
    int dst = clamp_idx(__ldg(&ei[E + e]), n);
    int p0 = atomicAdd(&g_cur_in[dst], 1);
    g_in_src[p0] = src;
    int p1 = atomicAdd(&g_cur_out[src], 1);
    g_out_dst[p1] = dst;
}

// ---------------------------------------------------------------------------
// Weight prep: split fp32 W[k][n] -> bf16 hi/lo, transposed to [n][k]
// ---------------------------------------------------------------------------
__global__ void prep_weights(const float* __restrict__ Wself,
                             const float* __restrict__ Ws2d,
                             const float* __restrict__ Wd2s) {
    int idx = blockIdx.x * blockDim.x + threadIdx.x;
    if (idx >= 3 * 16384) return;
    int chunk = idx >> 14;
    int rem   = idx & 16383;
    int k  = rem >> 7;
    int nn = rem & 127;
    const float* W = (chunk == 0) ? Wself : (chunk == 1) ? Ws2d : Wd2s;
    float w = __ldg(&W[k * 128 + nn]);
    __nv_bfloat16 hi = __float2bfloat16(w);
    float lo = w - __bfloat162float(hi);
    g_Bhi[chunk * 16384 + nn * 128 + k] = hi;
    g_Blo[chunk * 16384 + nn * 128 + k] = __float2bfloat16(lo);
}

// ---------------------------------------------------------------------------
// Gather: one warp per node, accumulate neighbor rows in registers, write
// packed bf16 hi/lo with 0.5/deg folded in. DIR 0 (in) also packs chunk 0 (x).
// ---------------------------------------------------------------------------
template<int DIR>
__global__ void __launch_bounds__(256)
gather_kernel(const float* __restrict__ x, int n) {
    int node = (blockIdx.x * blockDim.x + threadIdx.x) >> 5;
    int lane = threadIdx.x & 31;
    if (node >= n) return;

    const int* rp    = (DIR == 0) ? g_rp_in  : g_rp_out;
    const int* elist = (DIR == 0) ? g_in_src : g_out_dst;
    const int b  = rp[node];
    const int e2 = rp[node + 1];
    const int deg = e2 - b;

    float4 acc = make_float4(0.f, 0.f, 0.f, 0.f);
    int j = b;
    for (; j + 4 <= e2; j += 4) {
        int i0 = __ldg(&elist[j + 0]);
        int i1 = __ldg(&elist[j + 1]);
        int i2 = __ldg(&elist[j + 2]);
        int i3 = __ldg(&elist[j + 3]);
        float4 v0 = __ldg(reinterpret_cast<const float4*>(x + (size_t)i0 * DIM) + lane);
        float4 v1 = __ldg(reinterpret_cast<const float4*>(x + (size_t)i1 * DIM) + lane);
        float4 v2 = __ldg(reinterpret_cast<const float4*>(x + (size_t)i2 * DIM) + lane);
        float4 v3 = __ldg(reinterpret_cast<const float4*>(x + (size_t)i3 * DIM) + lane);
        acc.x += v0.x + v1.x + v2.x + v3.x;
        acc.y += v0.y + v1.y + v2.y + v3.y;
        acc.z += v0.z + v1.z + v2.z + v3.z;
        acc.w += v0.w + v1.w + v2.w + v3.w;
    }
    for (; j < e2; j++) {
        int i0 = __ldg(&elist[j]);
        float4 v0 = __ldg(reinterpret_cast<const float4*>(x + (size_t)i0 * DIM) + lane);
        acc.x += v0.x; acc.y += v0.y; acc.z += v0.z; acc.w += v0.w;
    }

    const float s = 0.5f / fmaxf((float)deg, 1.f);
    acc.x *= s; acc.y *= s; acc.z *= s; acc.w *= s;

    uint2 hi, lo;
    split4(acc, hi, lo);
    const size_t off = (size_t)node * 384 + (DIR == 0 ? 128 : 256) + lane * 4;
    *reinterpret_cast<uint2*>(g_Ahi + off) = hi;
    *reinterpret_cast<uint2*>(g_Alo + off) = lo;

    if (DIR == 0) {
        float4 v = __ldg(reinterpret_cast<const float4*>(x + (size_t)node * DIM) + lane);
        split4(v, hi, lo);
        const size_t o0 = (size_t)node * 384 + lane * 4;
        *reinterpret_cast<uint2*>(g_Ahi + o0) = hi;
        *reinterpret_cast<uint2*>(g_Alo + o0) = lo;
    }
}

// ---------------------------------------------------------------------------
// Pure-bf16 GEMM, cp.async 2-stage pipeline, occupancy 2:
//   out[N,128] = A[N,384] @ W(384x128) + bias, 3-term split hi/lo.
// BM=128, BN=64, BK=64 (6 steps); 8 warps, warp tile 32x32.
// Stage = A_hi|A_lo (128x144B) + B_hi|B_lo (64x144B) = 55296B; x2 = 110592.
// ---------------------------------------------------------------------------
#define TSTRIDE 144
#define APLANE  (128 * TSTRIDE)          // 18432
#define BPLANE  (64 * TSTRIDE)           // 9216
#define STAGE   (2 * APLANE + 2 * BPLANE)  // 55296

__global__ void __launch_bounds__(256, 2)
gemm_mma_kernel(const float* __restrict__ bself,
                const float* __restrict__ bs2d,
                const float* __restrict__ bd2s,
                float* __restrict__ out, int n) {
    extern __shared__ char smem[];
    const uint32_t sbase = smem_u32(smem);

    const int tid  = threadIdx.x;
    const int lane = tid & 31;
    const int wid  = tid >> 5;
    const int block_row = blockIdx.x * 128;
    const int ncol_base = blockIdx.y * 64;

    // warp tile: 32 rows x 32 cols
    const int m0  = (wid & 3) * 32;
    const int n0l = (wid >> 2) * 32;      // local within 64-col block

    // A fill: 2 threads/row, 64B each
    const int frow = tid >> 1;
    const int half = tid & 1;
    const int grow = min(block_row + frow, n - 1);
    // B fill: tid<128, 2 threads/row over 64 rows
    const int brow  = (tid & 127) >> 1;
    const int bhalf = tid & 1;

    auto issue_stage = [&](int s, int st) {
        const uint32_t buf = sbase + st * STAGE;
        // A planes
        {
            const uint32_t d = (uint32_t)frow * TSTRIDE + half * 64;
            const char* srcAh = (const char*)(g_Ahi + (size_t)grow * 384 + s * 64)
                              + half * 64;
            const char* srcAl = (const char*)(g_Alo + (size_t)grow * 384 + s * 64)
                              + half * 64;
#pragma unroll
            for (int jj = 0; jj < 4; jj++) {
                cp_async16(buf + d + jj * 16, srcAh + jj * 16);
                cp_async16(buf + APLANE + d + jj * 16, srcAl + jj * 16);
            }
        }
        // B planes (first 128 threads)
        if (tid < 128) {
            const int chunk = s >> 1;
            const int kh    = s & 1;
            const uint32_t d = (uint32_t)brow * TSTRIDE + bhalf * 64;
            const char* srcBh = (const char*)(g_Bhi + chunk * 16384
                                + (size_t)(ncol_base + brow) * 128 + kh * 64)
                              + bhalf * 64;
            const char* srcBl = (const char*)(g_Blo + chunk * 16384
                                + (size_t)(ncol_base + brow) * 128 + kh * 64)
                              + bhalf * 64;
#pragma unroll
            for (int jj = 0; jj < 4; jj++) {
                cp_async16(buf + 2 * APLANE + d + jj * 16, srcBh + jj * 16);
                cp_async16(buf + 2 * APLANE + BPLANE + d + jj * 16, srcBl + jj * 16);
            }
        }
    };

    const uint32_t offA = (uint32_t)(m0 + (lane & 15)) * TSTRIDE + ((lane >> 4) << 4);
    const uint32_t offB = (uint32_t)(n0l + ((lane >> 4) << 3) + (lane & 7)) * TSTRIDE
                        + (((lane >> 3) & 1) << 4);

    float acc[2][4][4];
#pragma unroll
    for (int m = 0; m < 2; m++)
#pragma unroll
        for (int f = 0; f < 4; f++)
#pragma unroll
            for (int r = 0; r < 4; r++) acc[m][f][r] = 0.f;

    issue_stage(0, 0); cp_commit();
    issue_stage(1, 1); cp_commit();

#pragma unroll 1
    for (int s = 0; s < 6; s++) {
        cp_wait1();
        __syncthreads();

        const uint32_t buf = sbase + (s & 1) * STAGE;
        const uint32_t aHi = buf, aLo = buf + APLANE;
        const uint32_t bHi = buf + 2 * APLANE, bLo = bHi + BPLANE;

#pragma unroll
        for (int ks = 0; ks < 4; ks++) {
            const uint32_t kb = (uint32_t)ks * 32;

            uint32_t ah[2][4], al[2][4];
#pragma unroll
            for (int m = 0; m < 2; m++) {
                uint32_t a = offA + (uint32_t)m * 16 * TSTRIDE + kb;
                ldsm_x4(ah[m], aHi + a);
                ldsm_x4(al[m], aLo + a);
            }
#pragma unroll
            for (int g = 0; g < 2; g++) {
                uint32_t b = offB + (uint32_t)g * 16 * TSTRIDE + kb;
                uint32_t bh[4], bl[4];
                ldsm_x4(bh, bHi + b);
                ldsm_x4(bl, bLo + b);
#pragma unroll
                for (int m = 0; m < 2; m++) {
                    mma_bf16(acc[m][2 * g + 0], ah[m], bh[0], bh[1]);
                    mma_bf16(acc[m][2 * g + 1], ah[m], bh[2], bh[3]);
                    mma_bf16(acc[m][2 * g + 0], ah[m], bl[0], bl[1]);
                    mma_bf16(acc[m][2 * g + 1], ah[m], bl[2], bl[3]);
                    mma_bf16(acc[m][2 * g + 0], al[m], bh[0], bh[1]);
                    mma_bf16(acc[m][2 * g + 1], al[m], bh[2], bh[3]);
                }
            }
        }

        __syncthreads();
        if (s + 2 < 6) issue_stage(s + 2, s & 1);
        cp_commit();
    }

    // ---- Epilogue: fused bias = b_self + 0.5*(b_s2d + b_d2s)
    const int colq = (lane & 3) * 2;
    const int rowq = lane >> 2;
#pragma unroll
    for (int f = 0; f < 4; f++) {
        int col = ncol_base + n0l + f * 8 + colq;
        float b0 = __ldg(&bself[col])     + 0.5f * (__ldg(&bs2d[col])     + __ldg(&bd2s[col]));
        float b1 = __ldg(&bself[col + 1]) + 0.5f * (__ldg(&bs2d[col + 1]) + __ldg(&bd2s[col + 1]));
#pragma unroll
        for (int m = 0; m < 2; m++) {
            int r0 = block_row + m0 + m * 16 + rowq;
#pragma unroll
            for (int h = 0; h < 2; h++) {
                int row = r0 + h * 8;
                if (row < n) {
                    float2 v = make_float2(acc[m][f][2 * h] + b0,
                                           acc[m][f][2 * h + 1] + b1);
                    *reinterpret_cast<float2*>(out + (size_t)row * DIM + col) = v;
                }
            }
        }
    }
}

// ---------------------------------------------------------------------------
// Launch
// ---------------------------------------------------------------------------
extern "C" void kernel_launch(void* const* d_in, const int* in_sizes, int n_in,
                              void* d_out, int out_size) {
    const float* x     = (const float*)d_in[0];
    const float* Wself = (const float*)d_in[1];
    const float* bself = (const float*)d_in[2];
    const float* Ws2d  = (const float*)d_in[3];
    const float* bs2d  = (const float*)d_in[4];
    const float* Wd2s  = (const float*)d_in[5];
    const float* bd2s  = (const float*)d_in[6];
    const int*   ei    = (const int*)d_in[7];

    int N = in_sizes[0] / DIM;      // 100000
    int E = in_sizes[7] / 2;        // 800000
    float* out = (float*)d_out;

    const int smem_bytes = 2 * STAGE;   // 110592
    cudaFuncSetAttribute(gemm_mma_kernel,
                         cudaFuncAttributeMaxDynamicSharedMemorySize, smem_bytes);

    const int nblk = (N + SCAN_BLK - 1) / SCAN_BLK;   // 98

    prep_weights<<<(3 * 16384 + 255) / 256, 256>>>(Wself, Ws2d, Wd2s);

    zero_hist_kernel<<<(N + 255) / 256, 256>>>(N);
    hist_kernel<<<(E + 255) / 256, 256>>>(ei, E, N);
    scan1_kernel<<<dim3(nblk, 2), SCAN_BLK>>>(N);
    scan2_kernel<<<1, 64>>>(nblk, N);
    scan3_kernel<<<dim3(nblk, 2), SCAN_BLK>>>(N);
    place_kernel<<<(E + 255) / 256, 256>>>(ei, E, N);

    gather_kernel<0><<<(N * 32 + 255) / 256, 256>>>(x, N);
    gather_kernel<1><<<(N * 32 + 255) / 256, 256>>>(x, N);

    dim3 grid((N + 127) / 128, 2);
    gemm_mma_kernel<<<grid, 256, smem_bytes>>>(bself, bs2d, bd2s, out, N);
}

// round 10
// speedup vs baseline: 2.2903x; 1.0249x over previous
#include <cuda_runtime.h>
#include <cuda_bf16.h>
#include <cstdint>

#define NMAX 100000
#define EMAX 800000
#define DIM 128
#define SCAN_BLK 1024
#define NBLK_MAX 128

// ---------------------------------------------------------------------------
// Scratch (__device__ globals per allocation-free rule)
// ---------------------------------------------------------------------------
// Packed A operand: [N][384] bf16 hi/lo planes (scales folded in)
__device__ __align__(16) __nv_bfloat16 g_Ahi[(size_t)NMAX * 384];
__device__ __align__(16) __nv_bfloat16 g_Alo[(size_t)NMAX * 384];
// Weights, bf16 split, TRANSPOSED to [chunk][n][k]  (B[n][k] = W[k][n])
__device__ __align__(16) __nv_bfloat16 g_Bhi[3 * 128 * 128];
__device__ __align__(16) __nv_bfloat16 g_Blo[3 * 128 * 128];
// CSR machinery
__device__ int g_hist_in[NMAX];
__device__ int g_hist_out[NMAX];
__device__ int g_rp_in[NMAX + 1];
__device__ int g_rp_out[NMAX + 1];
__device__ int g_cur_in[NMAX];
__device__ int g_cur_out[NMAX];
__device__ int g_part_in[NMAX];
__device__ int g_part_out[NMAX];
__device__ int g_bsum[2][NBLK_MAX];
__device__ int g_boff[2][NBLK_MAX];
__device__ int g_in_src[EMAX];    // src ids grouped by dst
__device__ int g_out_dst[EMAX];   // dst ids grouped by src

// ---------------------------------------------------------------------------
// helpers
// ---------------------------------------------------------------------------
__device__ __forceinline__ int clamp_idx(int v, int n) {
    return v < 0 ? 0 : (v >= n ? n - 1 : v);
}

__device__ __forceinline__ uint32_t smem_u32(const void* p) {
    uint32_t a;
    asm("{ .reg .u64 t; cvta.to.shared.u64 t, %1; cvt.u32.u64 %0, t; }"
        : "=r"(a) : "l"(p));
    return a;
}

__device__ __forceinline__ void cp_async16(uint32_t dst, const void* src) {
    asm volatile("cp.async.cg.shared.global [%0], [%1], 16;"
                 :: "r"(dst), "l"(src) : "memory");
}
__device__ __forceinline__ void cp_commit() {
    asm volatile("cp.async.commit_group;" ::: "memory");
}
__device__ __forceinline__ void cp_wait1() {
    asm volatile("cp.async.wait_group 1;" ::: "memory");
}

__device__ __forceinline__ void ldsm_x4(uint32_t* r, uint32_t addr) {
    asm volatile("ldmatrix.sync.aligned.m8n8.x4.shared.b16 {%0,%1,%2,%3}, [%4];"
                 : "=r"(r[0]), "=r"(r[1]), "=r"(r[2]), "=r"(r[3]) : "r"(addr));
}

__device__ __forceinline__ void mma_bf16(float* d, const uint32_t* a,
                                         uint32_t b0, uint32_t b1) {
    asm volatile(
        "mma.sync.aligned.m16n8k16.row.col.f32.bf16.bf16.f32 "
        "{%0,%1,%2,%3}, {%4,%5,%6,%7}, {%8,%9}, {%0,%1,%2,%3};"
        : "+f"(d[0]), "+f"(d[1]), "+f"(d[2]), "+f"(d[3])
        : "r"(a[0]), "r"(a[1]), "r"(a[2]), "r"(a[3]), "r"(b0), "r"(b1));
}

// split float4 -> bf16 hi/lo packed as uint2 each
__device__ __forceinline__ void split4(float4 v, uint2& hi, uint2& lo) {
    __nv_bfloat16 hx = __float2bfloat16(v.x);
    __nv_bfloat16 hy = __float2bfloat16(v.y);
    __nv_bfloat16 hz = __float2bfloat16(v.z);
    __nv_bfloat16 hw = __float2bfloat16(v.w);
    __nv_bfloat162 h01; h01.x = hx; h01.y = hy;
    __nv_bfloat162 h23; h23.x = hz; h23.y = hw;
    __nv_bfloat162 l01;
    l01.x = __float2bfloat16(v.x - __bfloat162float(hx));
    l01.y = __float2bfloat16(v.y - __bfloat162float(hy));
    __nv_bfloat162 l23;
    l23.x = __float2bfloat16(v.z - __bfloat162float(hz));
    l23.y = __float2bfloat16(v.w - __bfloat162float(hw));
    hi = make_uint2(*reinterpret_cast<uint32_t*>(&h01),
                    *reinterpret_cast<uint32_t*>(&h23));
    lo = make_uint2(*reinterpret_cast<uint32_t*>(&l01),
                    *reinterpret_cast<uint32_t*>(&l23));
}

// ---------------------------------------------------------------------------
// CSR build: hist -> 3-phase parallel exclusive scan -> place
// ---------------------------------------------------------------------------
__global__ void zero_hist_kernel(int n) {
    int i = blockIdx.x * blockDim.x + threadIdx.x;
    if (i < n) { g_hist_in[i] = 0; g_hist_out[i] = 0; }
}

__global__ void hist_kernel(const int* __restrict__ ei, int E, int n) {
    int e = blockIdx.x * blockDim.x + threadIdx.x;
    if (e >= E) return;
    int src = clamp_idx(__ldg(&ei[e]), n);
    int dst = clamp_idx(__ldg(&ei[E + e]), n);
    atomicAdd(&g_hist_in[dst],  1);
    atomicAdd(&g_hist_out[src], 1);
}

// phase 1: per-block exclusive scan (1024 elems/block), emit block totals
__global__ void __launch_bounds__(SCAN_BLK)
scan1_kernel(int n) {
    const int dir = blockIdx.y;
    const int b   = blockIdx.x;
    const int i   = b * SCAN_BLK + threadIdx.x;
    const int lane = threadIdx.x & 31;
    const int w    = threadIdx.x >> 5;

    const int* hist = (dir == 0) ? g_hist_in : g_hist_out;
    int v = (i < n) ? hist[i] : 0;

    // warp inclusive scan
    int x = v;
#pragma unroll
    for (int o = 1; o < 32; o <<= 1) {
        int t = __shfl_up_sync(~0u, x, o);
        if (lane >= o) x += t;
    }
    __shared__ int wsum[32];
    if (lane == 31) wsum[w] = x;
    __syncthreads();
    if (w == 0) {
        int y = wsum[lane];
#pragma unroll
        for (int o = 1; o < 32; o <<= 1) {
            int t = __shfl_up_sync(~0u, y, o);
            if (lane >= o) y += t;
        }
        wsum[lane] = y;
    }
    __syncthreads();
    int incl = x + (w > 0 ? wsum[w - 1] : 0);

    int* part = (dir == 0) ? g_part_in : g_part_out;
    if (i < n) part[i] = incl - v;
    if (threadIdx.x == SCAN_BLK - 1) g_bsum[dir][b] = incl;
}

// phase 2: scan block totals (warp 0: dir 0, warp 1: dir 1); write rp[n]
__global__ void scan2_kernel(int nblk, int n) {
    const int dir  = threadIdx.x >> 5;
    const int lane = threadIdx.x & 31;
    if (dir >= 2) return;
    int run = 0;
    for (int base = 0; base < nblk; base += 32) {
        int idx = base + lane;
        int v = (idx < nblk) ? g_bsum[dir][idx] : 0;
        int x = v;
#pragma unroll
        for (int o = 1; o < 32; o <<= 1) {
            int t = __shfl_up_sync(~0u, x, o);
            if (lane >= o) x += t;
        }
        if (idx < nblk) g_boff[dir][idx] = run + x - v;
        run += __shfl_sync(~0u, x, 31);
    }
    if (lane == 0) ((dir == 0) ? g_rp_in : g_rp_out)[n] = run;
}

// phase 3: add block offsets, write rp and cur
__global__ void __launch_bounds__(SCAN_BLK)
scan3_kernel(int n) {
    const int dir = blockIdx.y;
    const int i   = blockIdx.x * SCAN_BLK + threadIdx.x;
    if (i >= n) return;
    const int off = g_boff[dir][blockIdx.x];
    int val = ((dir == 0) ? g_part_in : g_part_out)[i] + off;
    if (dir == 0) { g_rp_in[i]  = val; g_cur_in[i]  = val; }
    else          { g_rp_out[i] = val; g_cur_out[i] = val; }
}

__global__ void place_kernel(const int* __restrict__ ei, int E, int n) {
    int e = blockIdx.x * blockDim.x + threadIdx.x;
    if (e >= E) return;
    int src = clamp_idx(__ldg(&ei[e]), n);
    int dst = clamp_idx(__ldg(&ei[E + e]), n);
    int p0 = atomicAdd(&g_cur_in[dst], 1);
    g_in_src[p0] = src;
    int p1 = atomicAdd(&g_cur_out[src], 1);
    g_out_dst[p1] = dst;
}

// ---------------------------------------------------------------------------
// Weight prep: split fp32 W[k][n] -> bf16 hi/lo, transposed to [n][k]
// ---------------------------------------------------------------------------
__global__ void prep_weights(const float* __restrict__ Wself,
                             const float* __restrict__ Ws2d,
                             const float* __restrict__ Wd2s) {
    int idx = blockIdx.x * blockDim.x + threadIdx.x;
    if (idx >= 3 * 16384) return;
    int chunk = idx >> 14;
    int rem   = idx & 16383;
    int k  = rem >> 7;
    int nn = rem & 127;
    const float* W = (chunk == 0) ? Wself : (chunk == 1) ? Ws2d : Wd2s;
    float w = __ldg(&W[k * 128 + nn]);
    __nv_bfloat16 hi = __float2bfloat16(w);
    float lo = w - __bfloat162float(hi);
    g_Bhi[chunk * 16384 + nn * 128 + k] = hi;
    g_Blo[chunk * 16384 + nn * 128 + k] = __float2bfloat16(lo);
}

// ---------------------------------------------------------------------------
// Gather (both directions in one launch; blockIdx.y = dir):
// one warp per node, accumulate neighbor rows in registers, write packed
// bf16 hi/lo with 0.5/deg folded in. dir 0 (in) also packs chunk 0 (x).
// ---------------------------------------------------------------------------
__global__ void __launch_bounds__(256)
gather_kernel(const float* __restrict__ x, int n) {
    int node = (blockIdx.x * blockDim.x + threadIdx.x) >> 5;
    int lane = threadIdx.x & 31;
    if (node >= n) return;
    const int dir = blockIdx.y;

    const int* rp    = (dir == 0) ? g_rp_in  : g_rp_out;
    const int* elist = (dir == 0) ? g_in_src : g_out_dst;
    const int b  = rp[node];
    const int e2 = rp[node + 1];
    const int deg = e2 - b;

    float4 acc = make_float4(0.f, 0.f, 0.f, 0.f);
    int j = b;
    for (; j + 4 <= e2; j += 4) {
        int i0 = __ldg(&elist[j + 0]);
        int i1 = __ldg(&elist[j + 1]);
        int i2 = __ldg(&elist[j + 2]);
        int i3 = __ldg(&elist[j + 3]);
        float4 v0 = __ldg(reinterpret_cast<const float4*>(x + (size_t)i0 * DIM) + lane);
        float4 v1 = __ldg(reinterpret_cast<const float4*>(x + (size_t)i1 * DIM) + lane);
        float4 v2 = __ldg(reinterpret_cast<const float4*>(x + (size_t)i2 * DIM) + lane);
        float4 v3 = __ldg(reinterpret_cast<const float4*>(x + (size_t)i3 * DIM) + lane);
        acc.x += v0.x + v1.x + v2.x + v3.x;
        acc.y += v0.y + v1.y + v2.y + v3.y;
        acc.z += v0.z + v1.z + v2.z + v3.z;
        acc.w += v0.w + v1.w + v2.w + v3.w;
    }
    for (; j < e2; j++) {
        int i0 = __ldg(&elist[j]);
        float4 v0 = __ldg(reinterpret_cast<const float4*>(x + (size_t)i0 * DIM) + lane);
        acc.x += v0.x; acc.y += v0.y; acc.z += v0.z; acc.w += v0.w;
    }

    const float s = 0.5f / fmaxf((float)deg, 1.f);
    acc.x *= s; acc.y *= s; acc.z *= s; acc.w *= s;

    uint2 hi, lo;
    split4(acc, hi, lo);
    const size_t off = (size_t)node * 384 + (dir == 0 ? 128 : 256) + lane * 4;
    *reinterpret_cast<uint2*>(g_Ahi + off) = hi;
    *reinterpret_cast<uint2*>(g_Alo + off) = lo;

    if (dir == 0) {
        float4 v = __ldg(reinterpret_cast<const float4*>(x + (size_t)node * DIM) + lane);
        split4(v, hi, lo);
        const size_t o0 = (size_t)node * 384 + lane * 4;
        *reinterpret_cast<uint2*>(g_Ahi + o0) = hi;
        *reinterpret_cast<uint2*>(g_Alo + o0) = lo;
    }
}

// ---------------------------------------------------------------------------
// Pure-bf16 GEMM, cp.async 2-stage pipeline, occupancy 2:
//   out[N,128] = A[N,384] @ W(384x128) + bias, 3-term split hi/lo.
// BM=128, BN=64, BK=64 (6 steps); 8 warps, warp tile 32x32.
// grid = (2, nrow_blocks): the two n-halves of a row block are adjacent in
// launch order so the second hits the A tile in L2 (halves A DRAM traffic).
// Stage = A_hi|A_lo (128x144B) + B_hi|B_lo (64x144B) = 55296B; x2 = 110592.
// ---------------------------------------------------------------------------
#define TSTRIDE 144
#define APLANE  (128 * TSTRIDE)          // 18432
#define BPLANE  (64 * TSTRIDE)           // 9216
#define STAGE   (2 * APLANE + 2 * BPLANE)  // 55296

__global__ void __launch_bounds__(256, 2)
gemm_mma_kernel(const float* __restrict__ bself,
                const float* __restrict__ bs2d,
                const float* __restrict__ bd2s,
                float* __restrict__ out, int n) {
    extern __shared__ char smem[];
    const uint32_t sbase = smem_u32(smem);

    const int tid  = threadIdx.x;
    const int lane = tid & 31;
    const int wid  = tid >> 5;
    const int block_row = blockIdx.y * 128;
    const int ncol_base = blockIdx.x * 64;

    // warp tile: 32 rows x 32 cols
    const int m0  = (wid & 3) * 32;
    const int n0l = (wid >> 2) * 32;      // local within 64-col block

    // A fill: 2 threads/row, 64B each
    const int frow = tid >> 1;
    const int half = tid & 1;
    const int grow = min(block_row + frow, n - 1);
    // B fill: tid<128, 2 threads/row over 64 rows
    const int brow  = (tid & 127) >> 1;
    const int bhalf = tid & 1;

    auto issue_stage = [&](int s, int st) {
        const uint32_t buf = sbase + st * STAGE;
        // A planes
        {
            const uint32_t d = (uint32_t)frow * TSTRIDE + half * 64;
            const char* srcAh = (const char*)(g_Ahi + (size_t)grow * 384 + s * 64)
                              + half * 64;
            const char* srcAl = (const char*)(g_Alo + (size_t)grow * 384 + s * 64)
                              + half * 64;
#pragma unroll
            for (int jj = 0; jj < 4; jj++) {
                cp_async16(buf + d + jj * 16, srcAh + jj * 16);
                cp_async16(buf + APLANE + d + jj * 16, srcAl + jj * 16);
            }
        }
        // B planes (first 128 threads)
        if (tid < 128) {
            const int chunk = s >> 1;
            const int kh    = s & 1;
            const uint32_t d = (uint32_t)brow * TSTRIDE + bhalf * 64;
            const char* srcBh = (const char*)(g_Bhi + chunk * 16384
                                + (size_t)(ncol_base + brow) * 128 + kh * 64)
                              + bhalf * 64;
            const char* srcBl = (const char*)(g_Blo + chunk * 16384
                                + (size_t)(ncol_base + brow) * 128 + kh * 64)
                              + bhalf * 64;
#pragma unroll
            for (int jj = 0; jj < 4; jj++) {
                cp_async16(buf + 2 * APLANE + d + jj * 16, srcBh + jj * 16);
                cp_async16(buf + 2 * APLANE + BPLANE + d + jj * 16, srcBl + jj * 16);
            }
        }
    };

    const uint32_t offA = (uint32_t)(m0 + (lane & 15)) * TSTRIDE + ((lane >> 4) << 4);
    const uint32_t offB = (uint32_t)(n0l + ((lane >> 4) << 3) + (lane & 7)) * TSTRIDE
                        + (((lane >> 3) & 1) << 4);

    float acc[2][4][4];
#pragma unroll
    for (int m = 0; m < 2; m++)
#pragma unroll
        for (int f = 0; f < 4; f++)
#pragma unroll
            for (int r = 0; r < 4; r++) acc[m][f][r] = 0.f;

    issue_stage(0, 0); cp_commit();
    issue_stage(1, 1); cp_commit();

#pragma unroll 1
    for (int s = 0; s < 6; s++) {
        cp_wait1();
        __syncthreads();

        const uint32_t buf = sbase + (s & 1) * STAGE;
        const uint32_t aHi = buf, aLo = buf + APLANE;
        const uint32_t bHi = buf + 2 * APLANE, bLo = bHi + BPLANE;

#pragma unroll
        for (int ks = 0; ks < 4; ks++) {
            const uint32_t kb = (uint32_t)ks * 32;

            uint32_t ah[2][4], al[2][4];
#pragma unroll
            for (int m = 0; m < 2; m++) {
                uint32_t a = offA + (uint32_t)m * 16 * TSTRIDE + kb;
                ldsm_x4(ah[m], aHi + a);
                ldsm_x4(al[m], aLo + a);
            }
#pragma unroll
            for (int g = 0; g < 2; g++) {
                uint32_t b = offB + (uint32_t)g * 16 * TSTRIDE + kb;
                uint32_t bh[4], bl[4];
                ldsm_x4(bh, bHi + b);
                ldsm_x4(bl, bLo + b);
#pragma unroll
                for (int m = 0; m < 2; m++) {
                    mma_bf16(acc[m][2 * g + 0], ah[m], bh[0], bh[1]);
                    mma_bf16(acc[m][2 * g + 1], ah[m], bh[2], bh[3]);
                    mma_bf16(acc[m][2 * g + 0], ah[m], bl[0], bl[1]);
                    mma_bf16(acc[m][2 * g + 1], ah[m], bl[2], bl[3]);
                    mma_bf16(acc[m][2 * g + 0], al[m], bh[0], bh[1]);
                    mma_bf16(acc[m][2 * g + 1], al[m], bh[2], bh[3]);
                }
            }
        }

        __syncthreads();
        if (s + 2 < 6) issue_stage(s + 2, s & 1);
        cp_commit();
    }

    // ---- Epilogue: fused bias = b_self + 0.5*(b_s2d + b_d2s)
    const int colq = (lane & 3) * 2;
    const int rowq = lane >> 2;
#pragma unroll
    for (int f = 0; f < 4; f++) {
        int col = ncol_base + n0l + f * 8 + colq;
        float b0 = __ldg(&bself[col])     + 0.5f * (__ldg(&bs2d[col])     + __ldg(&bd2s[col]));
        float b1 = __ldg(&bself[col + 1]) + 0.5f * (__ldg(&bs2d[col + 1]) + __ldg(&bd2s[col + 1]));
#pragma unroll
        for (int m = 0; m < 2; m++) {
            int r0 = block_row + m0 + m * 16 + rowq;
#pragma unroll
            for (int h = 0; h < 2; h++) {
                int row = r0 + h * 8;
                if (row < n) {
                    float2 v = make_float2(acc[m][f][2 * h] + b0,
                                           acc[m][f][2 * h + 1] + b1);
                    *reinterpret_cast<float2*>(out + (size_t)row * DIM + col) = v;
                }
            }
        }
    }
}

// ---------------------------------------------------------------------------
// Launch
// ---------------------------------------------------------------------------
extern "C" void kernel_launch(void* const* d_in, const int* in_sizes, int n_in,
                              void* d_out, int out_size) {
    const float* x     = (const float*)d_in[0];
    const float* Wself = (const float*)d_in[1];
    const float* bself = (const float*)d_in[2];
    const float* Ws2d  = (const float*)d_in[3];
    const float* bs2d  = (const float*)d_in[4];
    const float* Wd2s  = (const float*)d_in[5];
    const float* bd2s  = (const float*)d_in[6];
    const int*   ei    = (const int*)d_in[7];

    int N = in_sizes[0] / DIM;      // 100000
    int E = in_sizes[7] / 2;        // 800000
    float* out = (float*)d_out;

    const int smem_bytes = 2 * STAGE;   // 110592
    cudaFuncSetAttribute(gemm_mma_kernel,
                         cudaFuncAttributeMaxDynamicSharedMemorySize, smem_bytes);

    const int nblk = (N + SCAN_BLK - 1) / SCAN_BLK;   // 98

    prep_weights<<<(3 * 16384 + 255) / 256, 256>>>(Wself, Ws2d, Wd2s);

    zero_hist_kernel<<<(N + 255) / 256, 256>>>(N);
    hist_kernel<<<(E + 255) / 256, 256>>>(ei, E, N);
    scan1_kernel<<<dim3(nblk, 2), SCAN_BLK>>>(N);
    scan2_kernel<<<1, 64>>>(nblk, N);
    scan3_kernel<<<dim3(nblk, 2), SCAN_BLK>>>(N);
    place_kernel<<<(E + 255) / 256, 256>>>(ei, E, N);

    dim3 ggrid((N * 32 + 255) / 256, 2);
    gather_kernel<<<ggrid, 256>>>(x, N);

    dim3 grid(2, (N + 127) / 128);
    gemm_mma_kernel<<<grid, 256, smem_bytes>>>(bself, bs2d, bd2s, out, N);
}